// round 16
// baseline (speedup 1.0000x reference)
#include <cuda_runtime.h>
#include <cuda_bf16.h>
#include <cuda_fp16.h>
#include <stdint.h>

// Problem constants (fixed by the dataset)
#define N_NODES_MAX 50000
#define N_EDGES_MAX 800000
#define IN_F   128
#define HID    256
#define HID2   128
#define N_CLS  2

// ---------------- scratch (static device globals; no allocation) -------------
__device__ int   g_i64;
__device__ int   g_deg[N_NODES_MAX];
__device__ int   g_off[N_NODES_MAX + 1];
__device__ int   g_cursor[N_NODES_MAX];
__device__ int   g_part[256];
__device__ int   g_partoff[256];
__device__ __align__(16) float g_deginv[N_NODES_MAX];
__device__ __align__(16) int   g_src[N_EDGES_MAX];
// x converted to fp16 [N,128] (halves agg1 gather bytes)
__device__ __align__(16) __half g_xh[(size_t)N_NODES_MAX * IN_F];
// bf16 split planes of agg(x) [N,128]
__device__ __align__(16) __nv_bfloat16 g_aggh[(size_t)N_NODES_MAX * IN_F];
__device__ __align__(16) __nv_bfloat16 g_aggl[(size_t)N_NODES_MAX * IN_F];
// h1 = relu(agg(x)@W1+b1) stored as bf16 split planes [N,256]
__device__ __align__(16) __nv_bfloat16 g_h1h[(size_t)N_NODES_MAX * HID];
__device__ __align__(16) __nv_bfloat16 g_h1l[(size_t)N_NODES_MAX * HID];
// t = h1 @ W2^T (no bias/relu) [N,128] fp16
__device__ __align__(16) __half g_t[(size_t)N_NODES_MAX * HID2];
// split-precision weights
__device__ __align__(16) __nv_bfloat16 g_w1h[HID * IN_F],  g_w1l[HID * IN_F];
__device__ __align__(16) __nv_bfloat16 g_w2h[HID2 * HID],  g_w2l[HID2 * HID];

__device__ __forceinline__ uint32_t pack_bf2(float a, float b) {
    __nv_bfloat162 v = __floats2bfloat162_rn(a, b);
    return *(uint32_t*)&v;
}

__device__ __forceinline__ int edge_at(const void* edges, int E, int which, int e) {
    if (g_i64) {
        const long long* p = (const long long*)edges;
        return (int)p[(size_t)which * E + e];
    } else {
        const int* p = (const int*)edges;
        return p[(size_t)which * E + e];
    }
}

// ---------------- dtype detect -----------------------------------------------
__global__ void detect_dtype_kernel(const int* __restrict__ raw, int E) {
    __shared__ int nz;
    if (threadIdx.x == 0) nz = 0;
    __syncthreads();
    int samples = min(1024, E);
    for (int i = threadIdx.x; i < samples; i += blockDim.x) {
        if (raw[2 * i + 1] != 0) atomicOr(&nz, 1);
    }
    __syncthreads();
    if (threadIdx.x == 0) g_i64 = (nz == 0) ? 1 : 0;
}

// ---------------- CSR build --------------------------------------------------
__global__ void zero_deg_kernel(int n) {
    int i = blockIdx.x * blockDim.x + threadIdx.x;
    if (i < n) g_deg[i] = 0;
}

__global__ void hist_kernel(const void* __restrict__ edges, int E, int n) {
    int e = blockIdx.x * blockDim.x + threadIdx.x;
    if (e < E) {
        int d = edge_at(edges, E, 1, e);
        d = max(0, min(d, n - 1));
        atomicAdd(&g_deg[d], 1);
    }
}

__global__ void scan_partial_kernel(int n) {
    __shared__ int s[256];
    int b = blockIdx.x, t = threadIdx.x;
    int i = b * 256 + t;
    s[t] = (i < n) ? g_deg[i] : 0;
    __syncthreads();
    #pragma unroll
    for (int off = 128; off > 0; off >>= 1) {
        if (t < off) s[t] += s[t + off];
        __syncthreads();
    }
    if (t == 0) g_part[b] = s[0];
}

__global__ void scan_blocksums_kernel(int nb) {
    __shared__ int s[256];
    int t = threadIdx.x;
    int v = (t < nb) ? g_part[t] : 0;
    s[t] = v;
    __syncthreads();
    #pragma unroll
    for (int off = 1; off < 256; off <<= 1) {
        int u = (t >= off) ? s[t - off] : 0;
        __syncthreads();
        s[t] += u;
        __syncthreads();
    }
    if (t < nb) g_partoff[t] = s[t] - v;
}

__global__ void scan_final_kernel(int n) {
    __shared__ int s[256];
    int b = blockIdx.x, t = threadIdx.x;
    int i = b * 256 + t;
    int d = (i < n) ? g_deg[i] : 0;
    s[t] = d;
    __syncthreads();
    #pragma unroll
    for (int off = 1; off < 256; off <<= 1) {
        int u = (t >= off) ? s[t - off] : 0;
        __syncthreads();
        s[t] += u;
        __syncthreads();
    }
    int base = g_partoff[b];
    if (i < n) {
        int excl = base + s[t] - d;
        g_off[i]    = excl;
        g_cursor[i] = excl;
        g_deginv[i] = 1.0f / fmaxf((float)d, 1.0f);
        if (i == n - 1) g_off[n] = excl + d;
    }
}

__global__ void scatter_kernel(const void* __restrict__ edges, int E, int n) {
    int e = blockIdx.x * blockDim.x + threadIdx.x;
    if (e < E) {
        int d = edge_at(edges, E, 1, e);
        d = max(0, min(d, n - 1));
        int s = edge_at(edges, E, 0, e);
        s = max(0, min(s, n - 1));
        int p = atomicAdd(&g_cursor[d], 1);
        if (p >= 0 && p < N_EDGES_MAX) g_src[p] = s;
    }
}

// ---------------- conversions -------------------------------------------------
template <int WHICH>
__global__ void conv_w_kernel(const float* __restrict__ W, int n) {
    int i = blockIdx.x * blockDim.x + threadIdx.x;
    if (i >= n) return;
    float w = W[i];
    __nv_bfloat16 h = __float2bfloat16(w);
    __nv_bfloat16 l = __float2bfloat16(w - __bfloat162float(h));
    if (WHICH == 1) { g_w1h[i] = h; g_w1l[i] = l; }
    else            { g_w2h[i] = h; g_w2l[i] = l; }
}

// x fp32 -> fp16 (vectorized: each thread converts 4 elements)
__global__ void conv_x_kernel(const float* __restrict__ x, int n4) {
    int i = blockIdx.x * blockDim.x + threadIdx.x;
    if (i >= n4) return;
    float4 v = ((const float4*)x)[i];
    __half2 a = __floats2half2_rn(v.x, v.y);
    __half2 b = __floats2half2_rn(v.z, v.w);
    ((uint2*)g_xh)[i] = make_uint2(*(uint32_t*)&a, *(uint32_t*)&b);
}

// ------- agg1: warp/node gather of fp16 x (128-wide) -> bf16 split planes -----
// Each lane covers cols 4*lane..4*lane+3 via one uint2 (4 halves) per row.
__global__ void agg1_kernel(int M) {
    int gw   = (blockIdx.x * blockDim.x + threadIdx.x) >> 5;
    int lane = threadIdx.x & 31;
    if (gw >= M) return;
    int beg = g_off[gw];
    int end = g_off[gw + 1];

    float4 acc = make_float4(0.f, 0.f, 0.f, 0.f);
    int i = beg;
    for (; i + 3 < end; i += 4) {
        int s0 = g_src[i], s1 = g_src[i + 1], s2 = g_src[i + 2], s3 = g_src[i + 3];
        uint2 u0 = ((const uint2*)(g_xh + (size_t)s0 * IN_F))[lane];
        uint2 u1 = ((const uint2*)(g_xh + (size_t)s1 * IN_F))[lane];
        uint2 u2 = ((const uint2*)(g_xh + (size_t)s2 * IN_F))[lane];
        uint2 u3 = ((const uint2*)(g_xh + (size_t)s3 * IN_F))[lane];
        #pragma unroll
        for (int j = 0; j < 4; ++j) {
            uint2 u = (j == 0) ? u0 : (j == 1) ? u1 : (j == 2) ? u2 : u3;
            float2 f0 = __half22float2(*(__half2*)&u.x);
            float2 f1 = __half22float2(*(__half2*)&u.y);
            acc.x += f0.x; acc.y += f0.y; acc.z += f1.x; acc.w += f1.y;
        }
    }
    for (; i < end; ++i) {
        int s0 = g_src[i];
        uint2 u = ((const uint2*)(g_xh + (size_t)s0 * IN_F))[lane];
        float2 f0 = __half22float2(*(__half2*)&u.x);
        float2 f1 = __half22float2(*(__half2*)&u.y);
        acc.x += f0.x; acc.y += f0.y; acc.z += f1.x; acc.w += f1.y;
    }

    float dinv = g_deginv[gw];
    float vx = acc.x * dinv, vy = acc.y * dinv, vz = acc.z * dinv, vw = acc.w * dinv;
    float hx = __bfloat162float(__float2bfloat16(vx));
    float hy = __bfloat162float(__float2bfloat16(vy));
    float hz = __bfloat162float(__float2bfloat16(vz));
    float hw = __bfloat162float(__float2bfloat16(vw));
    size_t idx = (size_t)gw * IN_F + lane * 4;
    *(uint2*)&g_aggh[idx] = make_uint2(pack_bf2(hx, hy), pack_bf2(hz, hw));
    *(uint2*)&g_aggl[idx] = make_uint2(pack_bf2(vx - hx, vy - hy), pack_bf2(vz - hz, vw - hw));
}

// ---------------- bf16 split-precision tensor-core GEMM -----------------------
// OUT=1: C = relu(aggA @ W1^T + b1) stored as bf16 split planes (h1h/h1l), N=256
// OUT=2: C = h1 @ W2^T (raw, no bias/relu) -> g_t as fp16, N=128
#define SMP 40   // smem row pitch in bf16

__device__ __forceinline__ void mma_bf16(float* c, const uint32_t* a, const uint32_t* b) {
    asm volatile(
        "mma.sync.aligned.m16n8k16.row.col.f32.bf16.bf16.f32 "
        "{%0,%1,%2,%3}, {%4,%5,%6,%7}, {%8,%9}, {%0,%1,%2,%3};"
        : "+f"(c[0]), "+f"(c[1]), "+f"(c[2]), "+f"(c[3])
        : "r"(a[0]), "r"(a[1]), "r"(a[2]), "r"(a[3]), "r"(b[0]), "r"(b[1]));
}

__device__ __forceinline__ uint32_t lds_b32(const __nv_bfloat16* s, int row, int colb32) {
    return *(const uint32_t*)&s[row * SMP + colb32 * 2];
}

template <int K, int OUT>
__global__ void gemm_mma_kernel(const float* __restrict__ bias, int M, int N) {
    const __nv_bfloat16* __restrict__ Ah = (OUT == 1) ? g_aggh : g_h1h;
    const __nv_bfloat16* __restrict__ Al = (OUT == 1) ? g_aggl : g_h1l;
    const __nv_bfloat16* __restrict__ Wh = (OUT == 1) ? g_w1h : g_w2h;
    const __nv_bfloat16* __restrict__ Wl = (OUT == 1) ? g_w1l : g_w2l;

    __shared__ __align__(16) __nv_bfloat16 sAh[128 * SMP];
    __shared__ __align__(16) __nv_bfloat16 sAl[128 * SMP];
    __shared__ __align__(16) __nv_bfloat16 sBh[64 * SMP];
    __shared__ __align__(16) __nv_bfloat16 sBl[64 * SMP];

    int tid  = threadIdx.x;
    int wid  = tid >> 5;
    int lane = tid & 31;
    int g    = lane >> 2;
    int t    = lane & 3;
    int warpM = wid >> 1;
    int warpN = wid & 1;
    int m0 = blockIdx.y * 128;
    int n0 = blockIdx.x * 64;

    float c[2][4][4];
    #pragma unroll
    for (int mi = 0; mi < 2; ++mi)
        #pragma unroll
        for (int ni = 0; ni < 4; ++ni)
            #pragma unroll
            for (int j = 0; j < 4; ++j) c[mi][ni][j] = 0.f;

    int arow = tid >> 1, aseg = tid & 1;
    int brow = tid >> 2, bseg = tid & 3;

    for (int k0 = 0; k0 < K; k0 += 32) {
        {
            int m = m0 + arow;
            uint4 z = make_uint4(0, 0, 0, 0);
            uint4 h0 = z, h1 = z, l0 = z, l1 = z;
            if (m < M) {
                size_t go = (size_t)m * K + k0 + aseg * 16;
                h0 = *(const uint4*)&Ah[go];
                h1 = *(const uint4*)&Ah[go + 8];
                l0 = *(const uint4*)&Al[go];
                l1 = *(const uint4*)&Al[go + 8];
            }
            int so = arow * SMP + aseg * 16;
            *(uint4*)&sAh[so] = h0; *(uint4*)&sAh[so + 8] = h1;
            *(uint4*)&sAl[so] = l0; *(uint4*)&sAl[so + 8] = l1;
        }
        {
            size_t go = (size_t)(n0 + brow) * K + k0 + bseg * 8;
            int so = brow * SMP + bseg * 8;
            *(uint4*)&sBh[so] = *(const uint4*)&Wh[go];
            *(uint4*)&sBl[so] = *(const uint4*)&Wl[go];
        }
        __syncthreads();

        #pragma unroll
        for (int ks = 0; ks < 32; ks += 16) {
            int koff = ks >> 1;
            uint32_t ah[2][4], al[2][4];
            #pragma unroll
            for (int mi = 0; mi < 2; ++mi) {
                int rb = warpM * 32 + mi * 16;
                ah[mi][0] = lds_b32(sAh, rb + g,     koff + t);
                ah[mi][1] = lds_b32(sAh, rb + g + 8, koff + t);
                ah[mi][2] = lds_b32(sAh, rb + g,     koff + t + 4);
                ah[mi][3] = lds_b32(sAh, rb + g + 8, koff + t + 4);
                al[mi][0] = lds_b32(sAl, rb + g,     koff + t);
                al[mi][1] = lds_b32(sAl, rb + g + 8, koff + t);
                al[mi][2] = lds_b32(sAl, rb + g,     koff + t + 4);
                al[mi][3] = lds_b32(sAl, rb + g + 8, koff + t + 4);
            }
            uint32_t bh[4][2], bl[4][2];
            #pragma unroll
            for (int ni = 0; ni < 4; ++ni) {
                int nb = warpN * 32 + ni * 8;
                bh[ni][0] = lds_b32(sBh, nb + g, koff + t);
                bh[ni][1] = lds_b32(sBh, nb + g, koff + t + 4);
                bl[ni][0] = lds_b32(sBl, nb + g, koff + t);
                bl[ni][1] = lds_b32(sBl, nb + g, koff + t + 4);
            }
            #pragma unroll
            for (int mi = 0; mi < 2; ++mi)
                #pragma unroll
                for (int ni = 0; ni < 4; ++ni) {
                    mma_bf16(c[mi][ni], ah[mi], bh[ni]);
                    mma_bf16(c[mi][ni], ah[mi], bl[ni]);
                    mma_bf16(c[mi][ni], al[mi], bh[ni]);
                }
        }
        __syncthreads();
    }

    #pragma unroll
    for (int mi = 0; mi < 2; ++mi) {
        int row0 = m0 + warpM * 32 + mi * 16 + g;
        int row1 = row0 + 8;
        #pragma unroll
        for (int ni = 0; ni < 4; ++ni) {
            int col = n0 + warpN * 32 + ni * 8 + 2 * t;
            if (OUT == 1) {
                float b0 = bias[col], b1 = bias[col + 1];
                if (row0 < M) {
                    float v0 = fmaxf(c[mi][ni][0] + b0, 0.f);
                    float v1 = fmaxf(c[mi][ni][1] + b1, 0.f);
                    float h0 = __bfloat162float(__float2bfloat16(v0));
                    float h1 = __bfloat162float(__float2bfloat16(v1));
                    size_t o = (size_t)row0 * N + col;
                    *(uint32_t*)&g_h1h[o] = pack_bf2(h0, h1);
                    *(uint32_t*)&g_h1l[o] = pack_bf2(v0 - h0, v1 - h1);
                }
                if (row1 < M) {
                    float v0 = fmaxf(c[mi][ni][2] + b0, 0.f);
                    float v1 = fmaxf(c[mi][ni][3] + b1, 0.f);
                    float h0 = __bfloat162float(__float2bfloat16(v0));
                    float h1 = __bfloat162float(__float2bfloat16(v1));
                    size_t o = (size_t)row1 * N + col;
                    *(uint32_t*)&g_h1h[o] = pack_bf2(h0, h1);
                    *(uint32_t*)&g_h1l[o] = pack_bf2(v0 - h0, v1 - h1);
                }
            } else {
                if (row0 < M)
                    *(__half2*)&g_t[(size_t)row0 * N + col] =
                        __floats2half2_rn(c[mi][ni][0], c[mi][ni][1]);
                if (row1 < M)
                    *(__half2*)&g_t[(size_t)row1 * N + col] =
                        __floats2half2_rn(c[mi][ni][2], c[mi][ni][3]);
            }
        }
    }
}

// ---- agg2 + head fused: h2 = relu(deginv*sum t[src] + b2); out = h2@W3^T+b3 --
__global__ void agg2_head_kernel(const float* __restrict__ b2,
                                 const float* __restrict__ W3,
                                 const float* __restrict__ b3,
                                 float* __restrict__ out, int M) {
    int gw   = (blockIdx.x * blockDim.x + threadIdx.x) >> 5;
    int lane = threadIdx.x & 31;
    if (gw >= M) return;
    int beg = g_off[gw];
    int end = g_off[gw + 1];

    float4 acc = make_float4(0.f, 0.f, 0.f, 0.f);
    int i = beg;
    for (; i + 3 < end; i += 4) {
        int s0 = g_src[i], s1 = g_src[i + 1], s2 = g_src[i + 2], s3 = g_src[i + 3];
        uint2 u0 = ((const uint2*)(g_t + (size_t)s0 * HID2))[lane];
        uint2 u1 = ((const uint2*)(g_t + (size_t)s1 * HID2))[lane];
        uint2 u2 = ((const uint2*)(g_t + (size_t)s2 * HID2))[lane];
        uint2 u3 = ((const uint2*)(g_t + (size_t)s3 * HID2))[lane];
        #pragma unroll
        for (int j = 0; j < 4; ++j) {
            uint2 u = (j == 0) ? u0 : (j == 1) ? u1 : (j == 2) ? u2 : u3;
            float2 f0 = __half22float2(*(__half2*)&u.x);
            float2 f1 = __half22float2(*(__half2*)&u.y);
            acc.x += f0.x; acc.y += f0.y; acc.z += f1.x; acc.w += f1.y;
        }
    }
    for (; i < end; ++i) {
        int s0 = g_src[i];
        uint2 u = ((const uint2*)(g_t + (size_t)s0 * HID2))[lane];
        float2 f0 = __half22float2(*(__half2*)&u.x);
        float2 f1 = __half22float2(*(__half2*)&u.y);
        acc.x += f0.x; acc.y += f0.y; acc.z += f1.x; acc.w += f1.y;
    }

    float dinv = g_deginv[gw];
    float4 bb = ((const float4*)b2)[lane];
    float4 h2;
    h2.x = fmaxf(acc.x * dinv + bb.x, 0.f);
    h2.y = fmaxf(acc.y * dinv + bb.y, 0.f);
    h2.z = fmaxf(acc.z * dinv + bb.z, 0.f);
    h2.w = fmaxf(acc.w * dinv + bb.w, 0.f);

    float4 w0 = ((const float4*)W3)[lane];
    float4 w1 = ((const float4*)(W3 + HID2))[lane];
    float s0 = h2.x * w0.x + h2.y * w0.y + h2.z * w0.z + h2.w * w0.w;
    float s1 = h2.x * w1.x + h2.y * w1.y + h2.z * w1.z + h2.w * w1.w;
    #pragma unroll
    for (int off = 16; off > 0; off >>= 1) {
        s0 += __shfl_xor_sync(0xffffffffu, s0, off);
        s1 += __shfl_xor_sync(0xffffffffu, s1, off);
    }
    if (lane == 0) {
        out[(size_t)gw * 2 + 0] = s0 + b3[0];
        out[(size_t)gw * 2 + 1] = s1 + b3[1];
    }
}

// ---------------- launch -----------------------------------------------------
extern "C" void kernel_launch(void* const* d_in, const int* in_sizes, int n_in,
                              void* d_out, int out_size) {
    const float* x     = (const float*)d_in[0];
    const void*  edges = d_in[1];

    int wbase = 2;
    if (n_in >= 9 && in_sizes[2] <= 1) wbase = 3;
    const float* W1 = (const float*)d_in[wbase + 0];
    const float* b1 = (const float*)d_in[wbase + 1];
    const float* W2 = (const float*)d_in[wbase + 2];
    const float* b2 = (const float*)d_in[wbase + 3];
    const float* W3 = (const float*)d_in[wbase + 4];
    const float* b3 = (const float*)d_in[wbase + 5];
    float* out = (float*)d_out;

    int N = in_sizes[0] / IN_F;
    int E = in_sizes[1] / 2;
    if (N > N_NODES_MAX) N = N_NODES_MAX;
    if (E > N_EDGES_MAX) E = N_EDGES_MAX;

    int scanBlocks = (N + 255) / 256;

    detect_dtype_kernel<<<1, 256>>>((const int*)edges, E);
    zero_deg_kernel<<<(N + 255) / 256, 256>>>(N);
    conv_x_kernel<<<(N * IN_F / 4 + 255) / 256, 256>>>(x, N * IN_F / 4);
    conv_w_kernel<1><<<(HID * IN_F + 255) / 256, 256>>>(W1, HID * IN_F);
    conv_w_kernel<2><<<(HID2 * HID + 255) / 256, 256>>>(W2, HID2 * HID);
    hist_kernel<<<(E + 255) / 256, 256>>>(edges, E, N);
    scan_partial_kernel<<<scanBlocks, 256>>>(N);
    scan_blocksums_kernel<<<1, 256>>>(scanBlocks);
    scan_final_kernel<<<scanBlocks, 256>>>(N);
    scatter_kernel<<<(E + 255) / 256, 256>>>(edges, E, N);

    const int warpsPerBlock = 8;
    int aggBlocks = (N + warpsPerBlock - 1) / warpsPerBlock;

    // layer 1: agg(fp16 x) -> planes ; mma-gemm (+bias+relu) -> h1 bf16 planes
    agg1_kernel<<<aggBlocks, warpsPerBlock * 32>>>(N);
    {
        dim3 grid(HID / 64, (N + 127) / 128);
        gemm_mma_kernel<IN_F, 1><<<grid, 256>>>(b1, N, HID);
    }
    // layer 2 (reordered): t = h1 @ W2^T (fp16) ; then agg+bias+relu+head fused
    {
        dim3 grid(HID2 / 64, (N + 127) / 128);
        gemm_mma_kernel<HID, 2><<<grid, 256>>>(nullptr, N, HID2);
    }
    agg2_head_kernel<<<aggBlocks, warpsPerBlock * 32>>>(b2, W3, b3, out, N);
}